// round 11
// baseline (speedup 1.0000x reference)
#include <cuda_runtime.h>

#define Bb 4
#define Ss 1024
#define Dd 32
#define Hh 32
#define NBLK 128           // 4 batches x 32 row-slices
#define NTHR 512           // 16 warps
#define WPAD 33            // padded row stride (floats)

// partial sums: [b][h][slice]
__device__ float g_ps [Bb * Hh * 32];
__device__ float g_psv[Bb * Hh * 32];
__device__ unsigned g_cnt[Bb * 32];   // one counter per batch, 128B apart

__global__ void __launch_bounds__(NTHR, 1) foaa_fused(
    const float* __restrict__ x,
    const float* __restrict__ Wk, const float* __restrict__ bk,
    const float* __restrict__ Wv, const float* __restrict__ bv,
    const float* __restrict__ Wo, const float* __restrict__ bo,
    float* __restrict__ out)
{
    const int b     = blockIdx.x >> 5;
    const int slice = blockIdx.x & 31;
    const int tid   = threadIdx.x;
    const int w     = tid >> 5;
    const int lane  = tid & 31;

    __shared__ float wk_s[Hh * WPAD];
    __shared__ float wv_s[Hh * WPAD];
    __shared__ float wo_s[Dd * WPAD];
    __shared__ float sred[16 * WPAD], svred[16 * WPAD];
    __shared__ float c_s[Hh];
    __shared__ __align__(16) float y[Dd];
    __shared__ float s_bo[Dd], s_bv[Dd];
    __shared__ int   s_last;

    // ---- Preamble: weights -> smem (coalesced f4, pad-33 scatter) ----
    {
        int idx = tid & 255;
        const float* src = (tid < 256) ? Wk : Wv;
        float*       dst = (tid < 256) ? wk_s : wv_s;
        float4 v = ((const float4*)src)[idx];
        int e = idx * 4, r = e >> 5, c0 = e & 31;
        dst[r * WPAD + c0 + 0] = v.x;
        dst[r * WPAD + c0 + 1] = v.y;
        dst[r * WPAD + c0 + 2] = v.z;
        dst[r * WPAD + c0 + 3] = v.w;
    }
    if (tid < 256) {
        float4 v = ((const float4*)Wo)[tid];
        int e = tid * 4, r = e >> 5, c0 = e & 31;
        wo_s[r * WPAD + c0 + 0] = v.x;
        wo_s[r * WPAD + c0 + 1] = v.y;
        wo_s[r * WPAD + c0 + 2] = v.z;
        wo_s[r * WPAD + c0 + 3] = v.w;
    } else if (tid < 264) {
        ((float4*)s_bo)[tid - 256] = ((const float4*)bo)[tid - 256];
    } else if (tid < 272) {
        ((float4*)s_bv)[tid - 264] = ((const float4*)bv)[tid - 264];
    }
    __syncthreads();

    // ---- Per-lane head weights into registers (conflict-free LDS) ----
    float wkr[32], wvr[32];
    #pragma unroll
    for (int c = 0; c < 32; c++) {
        wkr[c] = wk_s[lane * WPAD + c];
        wvr[c] = wv_s[lane * WPAD + c];
    }

    // ---- Stage 1: warp w handles rows 2w, 2w+1 of its slice.
    //      lane = head; x rows read directly from global as uniform
    //      broadcast LDG.128 (1 line per instr, 16 independent loads).
    const float4* xr = (const float4*)
        (x + ((size_t)b * Ss + slice * 32 + w * 2) * Dd);

    float s = 0.0f, sv = 0.0f;
    #pragma unroll
    for (int rr = 0; rr < 2; rr++) {
        float kp0 = 0.f, kp1 = 0.f, vp0 = 0.f, vp1 = 0.f;
        #pragma unroll
        for (int q = 0; q < 8; q += 2) {
            float4 a  = xr[rr * 8 + q];
            float4 bq = xr[rr * 8 + q + 1];
            kp0 = fmaf(a.x,  wkr[4*q+0], kp0); kp0 = fmaf(a.y,  wkr[4*q+1], kp0);
            kp0 = fmaf(a.z,  wkr[4*q+2], kp0); kp0 = fmaf(a.w,  wkr[4*q+3], kp0);
            vp0 = fmaf(a.x,  wvr[4*q+0], vp0); vp0 = fmaf(a.y,  wvr[4*q+1], vp0);
            vp0 = fmaf(a.z,  wvr[4*q+2], vp0); vp0 = fmaf(a.w,  wvr[4*q+3], vp0);
            kp1 = fmaf(bq.x, wkr[4*q+4], kp1); kp1 = fmaf(bq.y, wkr[4*q+5], kp1);
            kp1 = fmaf(bq.z, wkr[4*q+6], kp1); kp1 = fmaf(bq.w, wkr[4*q+7], kp1);
            vp1 = fmaf(bq.x, wvr[4*q+4], vp1); vp1 = fmaf(bq.y, wvr[4*q+5], vp1);
            vp1 = fmaf(bq.z, wvr[4*q+6], vp1); vp1 = fmaf(bq.w, wvr[4*q+7], vp1);
        }
        float e = __expf(kp0 + kp1);       // bk cancels in softmax
        s += e;
        sv = fmaf(e, vp0 + vp1, sv);       // bv added in epilogue
    }
    sred [w * WPAD + lane] = s;
    svred[w * WPAD + lane] = sv;
    __syncthreads();

    // ---- Block-reduce 16 warps (fixed order), publish slice partials ----
    if (w == 0) {
        float S = 0.f, SV = 0.f;
        #pragma unroll
        for (int k2 = 0; k2 < 16; k2++) {
            S  += sred [k2 * WPAD + lane];
            SV += svred[k2 * WPAD + lane];
        }
        g_ps [(b * Hh + lane) * 32 + slice] = S;
        g_psv[(b * Hh + lane) * 32 + slice] = SV;
    }
    __syncthreads();   // STGs above ordered before tid0's release-add

    // ---- Arrive; last arriver for this batch runs the epilogue ----
    if (tid == 0) {
        unsigned c0;
        asm volatile("atom.acq_rel.gpu.global.add.u32 %0, [%1], 1;"
                     : "=r"(c0) : "l"(&g_cnt[b * 32]) : "memory");
        s_last = ((c0 & 31u) == 31u);
    }
    __syncthreads();
    if (!s_last) return;                 // 31 of 32 blocks exit here

    // ---- Epilogue (one block per batch): gather partials, finish
    //      softmax, 32x32 matvec, write the whole 128KB batch output ----
    if (tid < Hh) {
        const float4* ps4  = (const float4*)(g_ps  + (b * Hh + tid) * 32);
        const float4* psv4 = (const float4*)(g_psv + (b * Hh + tid) * 32);
        float S = 0.f, SV = 0.f;
        #pragma unroll
        for (int q = 0; q < 8; q++) {
            float4 a = __ldcg(ps4  + q);   // L2-fresh (bypass L1)
            float4 v = __ldcg(psv4 + q);
            S  += a.x + a.y + a.z + a.w;
            SV += v.x + v.y + v.z + v.w;
        }
        c_s[tid] = SV / S + s_bv[tid];
    }
    __syncthreads();

    if (tid < Dd) {
        float acc = s_bo[tid];
        #pragma unroll
        for (int h2 = 0; h2 < Hh; h2++)
            acc = fmaf(c_s[h2], wo_s[tid * WPAD + h2], acc);
        y[tid] = acc;
    }
    __syncthreads();

    float4* ob = (float4*)(out + (size_t)b * Ss * Dd);   // 8192 f4
    float4 v4 = ((const float4*)y)[tid & 7];
    #pragma unroll
    for (int k2 = 0; k2 < 16; k2++)
        ob[tid + k2 * NTHR] = v4;
}

extern "C" void kernel_launch(void* const* d_in, const int* in_sizes, int n_in,
                              void* d_out, int out_size)
{
    // metadata order: x, Wq, bq, Wk, bk, Wv, bv, Wo, bo
    const float* x  = (const float*)d_in[0];
    const float* Wk = (const float*)d_in[3];
    const float* bk = (const float*)d_in[4];
    const float* Wv = (const float*)d_in[5];
    const float* bv = (const float*)d_in[6];
    const float* Wo = (const float*)d_in[7];
    const float* bo = (const float*)d_in[8];
    float* out = (float*)d_out;

    foaa_fused<<<NBLK, NTHR>>>(x, Wk, bk, Wv, bv, Wo, bo, out);
}

// round 13
// speedup vs baseline: 1.2000x; 1.2000x over previous
#include <cuda_runtime.h>

#define Bb 4
#define Ss 1024
#define Dd 32
#define Hh 32
#define NBLK 128           // 4 batches x 32 row-slices
#define NTHR 256           // 8 warps; warp w handles rows 4w..4w+3
#define WPAD 33            // padded stride for scalar-read arrays
#define WPAD4 36           // padded stride (floats) for f4-read weight arrays

// partial sums: [b][h][slice]
__device__ float g_ps [Bb * Hh * 32];
__device__ float g_psv[Bb * Hh * 32];
__device__ unsigned g_cnt[Bb * 32];   // per-batch counters, 128B apart

__global__ void __launch_bounds__(NTHR, 1) foaa_fused(
    const float* __restrict__ x,
    const float* __restrict__ Wk, const float* __restrict__ bk,
    const float* __restrict__ Wv, const float* __restrict__ bv,
    const float* __restrict__ Wo, const float* __restrict__ bo,
    float* __restrict__ out)
{
    const int b     = blockIdx.x >> 5;
    const int slice = blockIdx.x & 31;
    const int tid   = threadIdx.x;
    const int w     = tid >> 5;
    const int lane  = tid & 31;

    __shared__ __align__(16) float4 xs4[Dd * Dd / 4];   // 32 rows x 8 f4
    __shared__ __align__(16) float wk_s[Hh * WPAD4];
    __shared__ __align__(16) float wv_s[Hh * WPAD4];
    __shared__ float wo_s[Dd * WPAD];
    __shared__ float sred[8 * WPAD], svred[8 * WPAD];
    __shared__ float c_s[Hh];
    __shared__ __align__(16) float y[Dd];
    __shared__ float s_bo[Dd], s_bv[Dd];

    // ---- Preamble: coalesced global -> smem ----
    {   // x slice: 256 f4, one per thread (issue first: largest latency)
        xs4[tid] = ((const float4*)(x + ((size_t)b * Ss + slice * 32) * Dd))[tid];
    }
    {   // Wk -> wk_s (pad-36, f4-aligned scatter; conflict-free)
        float4 v = ((const float4*)Wk)[tid];
        int e = tid * 4, r = e >> 5, c0 = e & 31;
        *(float4*)&wk_s[r * WPAD4 + c0] = v;
    }
    {   // Wv -> wv_s
        float4 v = ((const float4*)Wv)[tid];
        int e = tid * 4, r = e >> 5, c0 = e & 31;
        *(float4*)&wv_s[r * WPAD4 + c0] = v;
    }
    {   // Wo -> wo_s (pad-33, scalar scatter; read scalar later)
        float4 v = ((const float4*)Wo)[tid];
        int e = tid * 4, r = e >> 5, c0 = e & 31;
        wo_s[r * WPAD + c0 + 0] = v.x;
        wo_s[r * WPAD + c0 + 1] = v.y;
        wo_s[r * WPAD + c0 + 2] = v.z;
        wo_s[r * WPAD + c0 + 3] = v.w;
    }
    if (tid < 8)       ((float4*)s_bo)[tid]     = ((const float4*)bo)[tid];
    else if (tid < 16) ((float4*)s_bv)[tid - 8] = ((const float4*)bv)[tid - 8];
    __syncthreads();

    // ---- Per-lane head weights into registers (f4 LDS, conflict-free) ----
    float4 wk4[8], wv4[8];
    #pragma unroll
    for (int q = 0; q < 8; q++) {
        wk4[q] = *(const float4*)&wk_s[lane * WPAD4 + 4 * q];
        wv4[q] = *(const float4*)&wv_s[lane * WPAD4 + 4 * q];
    }

    // ---- Stage 1: warp w handles rows 4w..4w+3; lane = head ----
    float s = 0.0f, sv = 0.0f;
    #pragma unroll
    for (int rr = 0; rr < 4; rr++) {
        const float4* xr = xs4 + (w * 4 + rr) * 8;   // uniform broadcast LDS
        float kp0 = 0.f, kp1 = 0.f, vp0 = 0.f, vp1 = 0.f;
        #pragma unroll
        for (int q = 0; q < 8; q += 2) {
            float4 a  = xr[q];
            float4 bq = xr[q + 1];
            kp0 = fmaf(a.x,  wk4[q].x,   kp0); kp0 = fmaf(a.y,  wk4[q].y,   kp0);
            kp0 = fmaf(a.z,  wk4[q].z,   kp0); kp0 = fmaf(a.w,  wk4[q].w,   kp0);
            vp0 = fmaf(a.x,  wv4[q].x,   vp0); vp0 = fmaf(a.y,  wv4[q].y,   vp0);
            vp0 = fmaf(a.z,  wv4[q].z,   vp0); vp0 = fmaf(a.w,  wv4[q].w,   vp0);
            kp1 = fmaf(bq.x, wk4[q+1].x, kp1); kp1 = fmaf(bq.y, wk4[q+1].y, kp1);
            kp1 = fmaf(bq.z, wk4[q+1].z, kp1); kp1 = fmaf(bq.w, wk4[q+1].w, kp1);
            vp1 = fmaf(bq.x, wv4[q+1].x, vp1); vp1 = fmaf(bq.y, wv4[q+1].y, vp1);
            vp1 = fmaf(bq.z, wv4[q+1].z, vp1); vp1 = fmaf(bq.w, wv4[q+1].w, vp1);
        }
        float e = __expf(kp0 + kp1);       // bk cancels in softmax
        s += e;
        sv = fmaf(e, vp0 + vp1, sv);       // bv added in epilogue
    }
    sred [w * WPAD + lane] = s;
    svred[w * WPAD + lane] = sv;
    __syncthreads();

    // ---- Block-reduce 8 warps (fixed order), publish slice partials ----
    if (w == 0) {
        float S = 0.f, SV = 0.f;
        #pragma unroll
        for (int k2 = 0; k2 < 8; k2++) {
            S  += sred [k2 * WPAD + lane];
            SV += svred[k2 * WPAD + lane];
        }
        g_ps [(b * Hh + lane) * 32 + slice] = S;
        g_psv[(b * Hh + lane) * 32 + slice] = SV;
    }
    __syncthreads();   // STGs above ordered before tid0's release-add

    // ---- Per-batch grid barrier: release-add arrive + acquire poll ----
    if (tid == 0) {
        unsigned c0;
        asm volatile("atom.release.gpu.global.add.u32 %0, [%1], 1;"
                     : "=r"(c0) : "l"(&g_cnt[b * 32]) : "memory");
        unsigned target = ((c0 >> 5) + 1u) << 5;   // next multiple of 32
        unsigned vcur;
        do {
            asm volatile("ld.acquire.gpu.u32 %0, [%1];"
                         : "=r"(vcur) : "l"(&g_cnt[b * 32]) : "memory");
        } while (vcur < target);
    }
    __syncthreads();

    // ---- Epilogue (all blocks): gather batch partials, finish softmax,
    //      32x32 matvec, write this block's 4KB of broadcast output ----
    if (tid < Hh) {
        const float4* ps4  = (const float4*)(g_ps  + (b * Hh + tid) * 32);
        const float4* psv4 = (const float4*)(g_psv + (b * Hh + tid) * 32);
        float S = 0.f, SV = 0.f;
        #pragma unroll
        for (int q = 0; q < 8; q++) {
            float4 a = __ldcg(ps4  + q);   // L2-fresh
            float4 v = __ldcg(psv4 + q);
            S  += a.x + a.y + a.z + a.w;
            SV += v.x + v.y + v.z + v.w;
        }
        c_s[tid] = SV / S + s_bv[tid];
    }
    __syncthreads();

    if (tid < Dd) {
        float acc = s_bo[tid];
        #pragma unroll
        for (int h2 = 0; h2 < Hh; h2++)
            acc = fmaf(c_s[h2], wo_s[tid * WPAD + h2], acc);
        y[tid] = acc;
    }
    __syncthreads();

    // 256 f4 = 4KB for this slice, one store per thread
    ((float4*)(out + ((size_t)b * Ss + slice * 32) * Dd))[tid] =
        ((const float4*)y)[tid & 7];
}

extern "C" void kernel_launch(void* const* d_in, const int* in_sizes, int n_in,
                              void* d_out, int out_size)
{
    // metadata order: x, Wq, bq, Wk, bk, Wv, bv, Wo, bo
    const float* x  = (const float*)d_in[0];
    const float* Wk = (const float*)d_in[3];
    const float* bk = (const float*)d_in[4];
    const float* Wv = (const float*)d_in[5];
    const float* bv = (const float*)d_in[6];
    const float* Wo = (const float*)d_in[7];
    const float* bo = (const float*)d_in[8];
    float* out = (float*)d_out;

    foaa_fused<<<NBLK, NTHR>>>(x, Wk, bk, Wv, bv, Wo, bo, out);
}

// round 15
// speedup vs baseline: 1.2353x; 1.0294x over previous
#include <cuda_runtime.h>

#define Bb 4
#define Ss 1024
#define Dd 32
#define Hh 32
#define NBLK 128           // 4 batches x 32 row-slices
#define NTHR 256           // 8 warps; warp w handles rows 4w..4w+3
#define WPAD 33            // padded stride for scalar-read arrays
#define WPAD4 36           // padded stride (floats) for f4-read weight arrays

// partials, transposed for coalescing: g_p[b][slice][0][h]=S, [1][h]=SV
__device__ float g_p[Bb * 32 * 2 * Hh];
__device__ unsigned g_cnt[Bb * 32];   // per-batch counters, 128B apart

__global__ void __launch_bounds__(NTHR, 1) foaa_fused(
    const float* __restrict__ x,
    const float* __restrict__ Wk, const float* __restrict__ bk,
    const float* __restrict__ Wv, const float* __restrict__ bv,
    const float* __restrict__ Wo, const float* __restrict__ bo,
    float* __restrict__ out)
{
    const int b     = blockIdx.x >> 5;
    const int slice = blockIdx.x & 31;
    const int tid   = threadIdx.x;
    const int w     = tid >> 5;
    const int lane  = tid & 31;

    __shared__ __align__(16) float wk_s[Hh * WPAD4];
    __shared__ __align__(16) float wv_s[Hh * WPAD4];
    __shared__ float wo_s[Dd * WPAD];
    __shared__ float sred[8 * WPAD], svred[8 * WPAD];
    __shared__ float pss[32 * WPAD], psv[32 * WPAD];
    __shared__ float c_s[Hh];
    __shared__ __align__(16) float y[Dd];
    __shared__ float s_bo[Dd], s_bv[Dd];

    // ---- Preamble: weights -> smem (coalesced f4; pad-36 f4 scatter) ----
    {
        float4 vk = ((const float4*)Wk)[tid];
        float4 vv = ((const float4*)Wv)[tid];
        float4 vo = ((const float4*)Wo)[tid];
        int e = tid * 4, r = e >> 5, c0 = e & 31;
        *(float4*)&wk_s[r * WPAD4 + c0] = vk;
        *(float4*)&wv_s[r * WPAD4 + c0] = vv;
        wo_s[r * WPAD + c0 + 0] = vo.x;
        wo_s[r * WPAD + c0 + 1] = vo.y;
        wo_s[r * WPAD + c0 + 2] = vo.z;
        wo_s[r * WPAD + c0 + 3] = vo.w;
    }
    if (tid < 8)       ((float4*)s_bo)[tid]     = ((const float4*)bo)[tid];
    else if (tid < 16) ((float4*)s_bv)[tid - 8] = ((const float4*)bv)[tid - 8];
    __syncthreads();

    // ---- Per-lane head weights into registers (f4 LDS, conflict-free) ----
    float4 wk4[8], wv4[8];
    #pragma unroll
    for (int q = 0; q < 8; q++) {
        wk4[q] = *(const float4*)&wk_s[lane * WPAD4 + 4 * q];
        wv4[q] = *(const float4*)&wv_s[lane * WPAD4 + 4 * q];
    }

    // ---- Stage 1: warp w handles rows 4w..4w+3; lane = head.
    //      x read directly from global as uniform-broadcast LDG.128
    //      (1 line per load, 32 independent loads, front-batched).
    const float4* xr = (const float4*)
        (x + ((size_t)b * Ss + slice * 32 + w * 4) * Dd);

    float s = 0.0f, sv = 0.0f;
    #pragma unroll
    for (int rr = 0; rr < 4; rr++) {
        float kp0 = 0.f, kp1 = 0.f, vp0 = 0.f, vp1 = 0.f;
        #pragma unroll
        for (int q = 0; q < 8; q += 2) {
            float4 a  = xr[rr * 8 + q];
            float4 bq = xr[rr * 8 + q + 1];
            kp0 = fmaf(a.x,  wk4[q].x,   kp0); kp0 = fmaf(a.y,  wk4[q].y,   kp0);
            kp0 = fmaf(a.z,  wk4[q].z,   kp0); kp0 = fmaf(a.w,  wk4[q].w,   kp0);
            vp0 = fmaf(a.x,  wv4[q].x,   vp0); vp0 = fmaf(a.y,  wv4[q].y,   vp0);
            vp0 = fmaf(a.z,  wv4[q].z,   vp0); vp0 = fmaf(a.w,  wv4[q].w,   vp0);
            kp1 = fmaf(bq.x, wk4[q+1].x, kp1); kp1 = fmaf(bq.y, wk4[q+1].y, kp1);
            kp1 = fmaf(bq.z, wk4[q+1].z, kp1); kp1 = fmaf(bq.w, wk4[q+1].w, kp1);
            vp1 = fmaf(bq.x, wv4[q+1].x, vp1); vp1 = fmaf(bq.y, wv4[q+1].y, vp1);
            vp1 = fmaf(bq.z, wv4[q+1].z, vp1); vp1 = fmaf(bq.w, wv4[q+1].w, vp1);
        }
        float e = __expf(kp0 + kp1);       // bk cancels in softmax
        s += e;
        sv = fmaf(e, vp0 + vp1, sv);       // bv added in epilogue
    }
    sred [w * WPAD + lane] = s;
    svred[w * WPAD + lane] = sv;
    __syncthreads();

    // ---- Block-reduce 8 warps (fixed order); publish 256B coalesced ----
    if (w == 0) {
        float S = 0.f, SV = 0.f;
        #pragma unroll
        for (int k2 = 0; k2 < 8; k2++) {
            S  += sred [k2 * WPAD + lane];
            SV += svred[k2 * WPAD + lane];
        }
        float* dst = g_p + (b * 32 + slice) * 2 * Hh;
        dst[lane]      = S;     // coalesced 128B
        dst[Hh + lane] = SV;    // coalesced 128B
    }
    __syncthreads();   // STGs above ordered before tid0's release-add

    // ---- Per-batch grid barrier: release-add arrive + acquire poll ----
    if (tid == 0) {
        unsigned c0;
        asm volatile("atom.release.gpu.global.add.u32 %0, [%1], 1;"
                     : "=r"(c0) : "l"(&g_cnt[b * 32]) : "memory");
        unsigned target = ((c0 >> 5) + 1u) << 5;   // next multiple of 32
        unsigned vcur;
        do {
            asm volatile("ld.acquire.gpu.u32 %0, [%1];"
                         : "=r"(vcur) : "l"(&g_cnt[b * 32]) : "memory");
        } while (vcur < target);
    }
    __syncthreads();

    // ---- Epilogue: coalesced 8KB gather of this batch's partials ----
    {
        const float4* src = (const float4*)(g_p + b * 2048);
        #pragma unroll
        for (int k2 = 0; k2 < 2; k2++) {
            int f = tid + k2 * NTHR;            // f4 index in [0,512)
            float4 v = __ldcg(src + f);         // L2-fresh
            int sl = f >> 4, part = (f >> 3) & 1, c0 = (f & 7) * 4;
            float* dst = (part ? psv : pss) + sl * WPAD + c0;
            dst[0] = v.x; dst[1] = v.y; dst[2] = v.z; dst[3] = v.w;
        }
    }
    __syncthreads();

    if (w == 0) {   // lane = head: fixed-order sum over 32 slices
        float S = 0.f, SV = 0.f;
        #pragma unroll
        for (int sl = 0; sl < 32; sl++) {
            S  += pss[sl * WPAD + lane];
            SV += psv[sl * WPAD + lane];
        }
        c_s[lane] = __fdividef(SV, S) + s_bv[lane];
    }
    __syncthreads();

    if (tid < Dd) {
        float acc = s_bo[tid];
        #pragma unroll
        for (int h2 = 0; h2 < Hh; h2++)
            acc = fmaf(c_s[h2], wo_s[tid * WPAD + h2], acc);
        y[tid] = acc;
    }
    __syncthreads();

    // 256 f4 = 4KB broadcast output for this slice
    ((float4*)(out + ((size_t)b * Ss + slice * 32) * Dd))[tid] =
        ((const float4*)y)[tid & 7];
}

extern "C" void kernel_launch(void* const* d_in, const int* in_sizes, int n_in,
                              void* d_out, int out_size)
{
    // metadata order: x, Wq, bq, Wk, bk, Wv, bv, Wo, bo
    const float* x  = (const float*)d_in[0];
    const float* Wk = (const float*)d_in[3];
    const float* bk = (const float*)d_in[4];
    const float* Wv = (const float*)d_in[5];
    const float* bv = (const float*)d_in[6];
    const float* Wo = (const float*)d_in[7];
    const float* bo = (const float*)d_in[8];
    float* out = (float*)d_out;

    foaa_fused<<<NBLK, NTHR>>>(x, Wk, bk, Wv, bv, Wo, bo, out);
}